// round 16
// baseline (speedup 1.0000x reference)
#include <cuda_runtime.h>
#include <cuda_bf16.h>
#include <cstdint>

#define F_DIM   512
#define F4      (F_DIM / 4)     // 128 float4 per row
#define NGROUPS 1024
#define OUTK    7
#define TPB     128             // one float4 column per thread, 4 warps

// Pairwise-combine scratch: zero-init .bss; the second-arriving sibling
// re-zeros its group's slots, so every launch/replay sees zeros on entry.
__device__ float    g_part[NGROUPS][8];   // 7 dot partials (+pad)
__device__ unsigned g_flag[NGROUPS];      // sibling arrival counter

// ---------------------------------------------------------------------------
// Grid = 2*NGROUPS. Block b handles HALF of group g=b>>1 (half = b&1):
//   [lo, hi) from the parallel 3-round probe (identical to champion R8);
//   this block streams [lo,mid) or [mid,hi), mid = lo + cnt/2.
// Halved work granularity shrinks the per-SM Poisson imbalance tail.
// Siblings combine via returned-value atomics (completion-ordered, pairwise —
// no grid-wide barrier, no fences): second arrival divides, biases, writes
// out, and re-zeros the scratch.
// ---------------------------------------------------------------------------
__global__ __launch_bounds__(TPB, 8)
void mognn_kernel(const float4* __restrict__ x4,
                  const int*    __restrict__ bw,   // batch as 32-bit words
                  const float4* __restrict__ W4g,
                  const float*  __restrict__ bias,
                  float*        __restrict__ out,
                  int N)
{
    const int g    = blockIdx.x >> 1;
    const int half = blockIdx.x & 1;
    const int t = threadIdx.x;          // 0..127 == float4 column
    const int warp = t >> 5, lane = t & 31;

    // --- dtype probe (batch sorted 0..1023, last element nonzero):
    // int64 storage => odd 32-bit words (high words) are zero. L2-hot.
    const bool is64 = (bw[N - 1] == 0) && (bw[N - 3] == 0) && (bw[N - 5] == 0);
    auto bval = [&](int i) -> int { return is64 ? bw[2 * i] : bw[i]; };

    __shared__ int   sm[4];
    __shared__ float redw[4][OUTK];
    __shared__ float s_sink[8];
    __shared__ int   s_second;

    const int BIG = NGROUPS + 1;
    // team: warps 0,1 -> lo (target g); warps 2,3 -> hi (target g+1)
    const int team   = (t >= 64);
    const int tt     = t & 63;
    const int target = team ? (g + 1) : g;

    int lo, hi;
    {
        // ---- round 1: shared probes @ stride1
        const int stride1 = (N + TPB - 1) / TPB;          // 782 for N=100000
        int idx = min(t * stride1, N - 1);
        int v = bval(idx);
        int c_lo = (v < g)     ? idx : -1;
        int c_hi = (v < g + 1) ? idx : -1;
        #pragma unroll
        for (int off = 16; off > 0; off >>= 1) {
            c_lo = max(c_lo, __shfl_xor_sync(0xffffffff, c_lo, off));
            c_hi = max(c_hi, __shfl_xor_sync(0xffffffff, c_hi, off));
        }
        if (lane == 0) { sm[warp] = c_lo; }
        __syncthreads();
        int a_lo = max(max(sm[0], sm[1]), max(sm[2], sm[3]));
        __syncthreads();
        if (lane == 0) { sm[warp] = c_hi; }
        __syncthreads();
        int a_hi = max(max(sm[0], sm[1]), max(sm[2], sm[3]));
        __syncthreads();

        // ---- round 2: two teams, stride2 probes
        const int stride2 = (stride1 + 63) / 64;          // 13
        int abase = team ? a_hi : a_lo;
        int pos = abase + 1 + tt * stride2;
        int v2 = (pos < N) ? bval(pos) : BIG;
        int c = (v2 < target) ? pos : -1;
        #pragma unroll
        for (int off = 16; off > 0; off >>= 1)
            c = max(c, __shfl_xor_sync(0xffffffff, c, off));
        if (lane == 0) sm[warp] = c;
        __syncthreads();
        int best_lo = max(a_lo, max(sm[0], sm[1]));
        int best_hi = max(a_hi, max(sm[2], sm[3]));
        __syncthreads();

        // ---- round 3: final <=stride2 positions, one parallel load
        abase = team ? best_hi : best_lo;
        pos = abase + 1 + tt;
        int v3 = (tt < stride2 && pos < N) ? bval(pos) : BIG;
        c = (v3 < target) ? pos : -1;
        #pragma unroll
        for (int off = 16; off > 0; off >>= 1)
            c = max(c, __shfl_xor_sync(0xffffffff, c, off));
        if (lane == 0) sm[warp] = c;
        __syncthreads();
        lo = max(best_lo, max(sm[0], sm[1])) + 1;
        hi = max(best_hi, max(sm[2], sm[3])) + 1;
    }
    const int cnt = hi - lo;

    // --- this block's half of the group
    const int mid = lo + (cnt >> 1);
    const int r0 = half ? mid : lo;
    const int r1 = half ? hi  : mid;

    // --- stream rows: 8 streaming (evict-first) loads in flight, 4 accums
    float4 a0 = make_float4(0.f, 0.f, 0.f, 0.f);
    float4 a1 = make_float4(0.f, 0.f, 0.f, 0.f);
    float4 a2 = make_float4(0.f, 0.f, 0.f, 0.f);
    float4 a3 = make_float4(0.f, 0.f, 0.f, 0.f);
    const float4* p = x4 + (size_t)r0 * F4 + t;
    int n = r1 - r0;
    for (; n >= 8; n -= 8, p += 8 * F4) {
        float4 v0 = __ldcs(p + 0 * F4);
        float4 v1 = __ldcs(p + 1 * F4);
        float4 v2 = __ldcs(p + 2 * F4);
        float4 v3 = __ldcs(p + 3 * F4);
        float4 v4 = __ldcs(p + 4 * F4);
        float4 v5 = __ldcs(p + 5 * F4);
        float4 v6 = __ldcs(p + 6 * F4);
        float4 v7 = __ldcs(p + 7 * F4);
        a0.x += v0.x; a0.y += v0.y; a0.z += v0.z; a0.w += v0.w;
        a1.x += v1.x; a1.y += v1.y; a1.z += v1.z; a1.w += v1.w;
        a2.x += v2.x; a2.y += v2.y; a2.z += v2.z; a2.w += v2.w;
        a3.x += v3.x; a3.y += v3.y; a3.z += v3.z; a3.w += v3.w;
        a0.x += v4.x; a0.y += v4.y; a0.z += v4.z; a0.w += v4.w;
        a1.x += v5.x; a1.y += v5.y; a1.z += v5.z; a1.w += v5.w;
        a2.x += v6.x; a2.y += v6.y; a2.z += v6.z; a2.w += v6.w;
        a3.x += v7.x; a3.y += v7.y; a3.z += v7.z; a3.w += v7.w;
    }
    for (; n > 0; n--, p += F4) {
        float4 v = __ldcs(p);
        a0.x += v.x; a0.y += v.y; a0.z += v.z; a0.w += v.w;
    }
    a0.x += a1.x; a0.y += a1.y; a0.z += a1.z; a0.w += a1.w;
    a2.x += a3.x; a2.y += a3.y; a2.z += a3.z; a2.w += a3.w;
    a0.x += a2.x; a0.y += a2.y; a0.z += a2.z; a0.w += a2.w;

    // --- 7 partial dots against W (tiny, L2-resident)
    float pr[OUTK];
    #pragma unroll
    for (int k = 0; k < OUTK; k++) {
        float4 w = __ldg(&W4g[k * F4 + t]);
        pr[k] = a0.x * w.x + a0.y * w.y + a0.z * w.z + a0.w * w.w;
    }

    // --- reduce across 4 warps
    #pragma unroll
    for (int off = 16; off > 0; off >>= 1) {
        #pragma unroll
        for (int k = 0; k < OUTK; k++)
            pr[k] += __shfl_xor_sync(0xffffffff, pr[k], off);
    }
    if (lane == 0) {
        #pragma unroll
        for (int k = 0; k < OUTK; k++) redw[warp][k] = pr[k];
    }
    __syncthreads();

    // --- pairwise sibling combine (completion-ordered, no fences)
    // 1) add partials with RETURNED-VALUE atomics; parking the result forces
    //    the scoreboard wait -> adds complete at L2 before the syncthreads.
    if (t < OUTK)
        s_sink[t] = atomicAdd(&g_part[g][t],
                    redw[0][t] + redw[1][t] + redw[2][t] + redw[3][t]);
    __syncthreads();
    // 2) bump arrival flag; second arrival finalizes.
    if (t == 0) {
        unsigned prev = atomicAdd(&g_flag[g], 1u);
        s_second = (prev == 1u) ? 1 : 0;
    }
    __syncthreads();
    if (s_second && t < OUTK) {
        // first sibling's adds completed before its flag bump (same ordering
        // argument); read L2-direct.
        float v = __ldcg(&g_part[g][t]);
        out[g * OUTK + t] = v / fmaxf((float)cnt, 1.0f) + bias[t];
        g_part[g][t] = 0.0f;               // restore zero invariant
        if (t == 0) g_flag[g] = 0u;        // reset for next replay
    }
}

// ---------------------------------------------------------------------------
// Inputs (metadata order):
//   d_in[0] = x          float32 [100000, 512]
//   d_in[1] = edge_index (unused)
//   d_in[2] = edge_attr  (unused)
//   d_in[3] = batch      int64-or-int32 [100000] (probed in-kernel)
//   d_in[4] = W          float32 [7, 512]
//   d_in[5] = b          float32 [7]
// Output: float32 [1024, 7]
// ---------------------------------------------------------------------------
extern "C" void kernel_launch(void* const* d_in, const int* in_sizes, int n_in,
                              void* d_out, int out_size)
{
    const float4* x4  = (const float4*)d_in[0];
    const int*    bw  = (const int*)d_in[3];
    const float4* W4g = (const float4*)d_in[4];
    const float*  b   = (const float*)d_in[5];
    float*        out = (float*)d_out;

    const int N = in_sizes[3];

    mognn_kernel<<<2 * NGROUPS, TPB>>>(x4, bw, W4g, b, out, N);
}

// round 17
// speedup vs baseline: 1.0553x; 1.0553x over previous
#include <cuda_runtime.h>
#include <cuda_bf16.h>
#include <cstdint>

#define F_DIM   512
#define F4      (F_DIM / 4)     // 128 float4 per row
#define NGROUPS 1024
#define OUTK    7
#define TPB     128             // one float4 column per thread, 4 warps

// ---------------------------------------------------------------------------
// Single fused kernel (champion, R8). Block g owns group g exclusively
// (batch is sorted):
//   [lo, hi) = [lower_bound(batch, g), lower_bound(batch, g+1))
// found by a fully parallel 3-round probe. Then stream rows with an 8-deep
// load pipeline using evict-first (streaming) loads — x is read exactly once
// and must not pollute L2 — dot with W, write out[g][:] = sum·Wᵀ/cnt + bias.
// Single launch, single wave (1024 blocks @ 8/SM), no scratch, no atomics.
// ---------------------------------------------------------------------------
__global__ __launch_bounds__(TPB, 8)
void mognn_kernel(const float4* __restrict__ x4,
                  const int*    __restrict__ bw,   // batch as 32-bit words
                  const float4* __restrict__ W4g,
                  const float*  __restrict__ bias,
                  float*        __restrict__ out,
                  int N)
{
    const int g = blockIdx.x;
    const int t = threadIdx.x;          // 0..127 == float4 column
    const int warp = t >> 5, lane = t & 31;

    // --- dtype probe (batch sorted 0..1023, last element nonzero):
    // int64 storage => odd 32-bit words (high words) are zero. L2-hot.
    const bool is64 = (bw[N - 1] == 0) && (bw[N - 3] == 0) && (bw[N - 5] == 0);
    auto bval = [&](int i) -> int { return is64 ? bw[2 * i] : bw[i]; };

    __shared__ int  sm[4];
    __shared__ float redw[4][OUTK];

    const int BIG = NGROUPS + 1;
    // team: warps 0,1 -> lo (target g); warps 2,3 -> hi (target g+1)
    const int team   = (t >= 64);
    const int tt     = t & 63;
    const int target = team ? (g + 1) : g;

    int lo, hi;
    {
        // ---- round 1: shared probes @ stride1
        const int stride1 = (N + TPB - 1) / TPB;          // 782 for N=100000
        int idx = min(t * stride1, N - 1);
        int v = bval(idx);
        int c_lo = (v < g)     ? idx : -1;
        int c_hi = (v < g + 1) ? idx : -1;
        #pragma unroll
        for (int off = 16; off > 0; off >>= 1) {
            c_lo = max(c_lo, __shfl_xor_sync(0xffffffff, c_lo, off));
            c_hi = max(c_hi, __shfl_xor_sync(0xffffffff, c_hi, off));
        }
        if (lane == 0) { sm[warp] = c_lo; }
        __syncthreads();
        int a_lo = max(max(sm[0], sm[1]), max(sm[2], sm[3]));
        __syncthreads();
        if (lane == 0) { sm[warp] = c_hi; }
        __syncthreads();
        int a_hi = max(max(sm[0], sm[1]), max(sm[2], sm[3]));
        __syncthreads();
        // boundary_lo in (a_lo, a_lo+stride1], same for hi.

        // ---- round 2: two teams, stride2 probes
        const int stride2 = (stride1 + 63) / 64;          // 13
        int abase = team ? a_hi : a_lo;
        int pos = abase + 1 + tt * stride2;
        int v2 = (pos < N) ? bval(pos) : BIG;
        int c = (v2 < target) ? pos : -1;
        #pragma unroll
        for (int off = 16; off > 0; off >>= 1)
            c = max(c, __shfl_xor_sync(0xffffffff, c, off));
        if (lane == 0) sm[warp] = c;
        __syncthreads();
        int best_lo = max(a_lo, max(sm[0], sm[1]));
        int best_hi = max(a_hi, max(sm[2], sm[3]));
        __syncthreads();
        // boundary in (best, best+stride2]

        // ---- round 3: final <=stride2 positions, one parallel load
        abase = team ? best_hi : best_lo;
        pos = abase + 1 + tt;
        int v3 = (tt < stride2 && pos < N) ? bval(pos) : BIG;
        c = (v3 < target) ? pos : -1;
        #pragma unroll
        for (int off = 16; off > 0; off >>= 1)
            c = max(c, __shfl_xor_sync(0xffffffff, c, off));
        if (lane == 0) sm[warp] = c;
        __syncthreads();
        lo = max(best_lo, max(sm[0], sm[1])) + 1;
        hi = max(best_hi, max(sm[2], sm[3])) + 1;
    }
    const int cnt = hi - lo;

    // --- stream rows: 8 streaming (evict-first) loads in flight, 4 accums
    float4 a0 = make_float4(0.f, 0.f, 0.f, 0.f);
    float4 a1 = make_float4(0.f, 0.f, 0.f, 0.f);
    float4 a2 = make_float4(0.f, 0.f, 0.f, 0.f);
    float4 a3 = make_float4(0.f, 0.f, 0.f, 0.f);
    const float4* p = x4 + (size_t)lo * F4 + t;
    int n = cnt;
    for (; n >= 8; n -= 8, p += 8 * F4) {
        float4 v0 = __ldcs(p + 0 * F4);
        float4 v1 = __ldcs(p + 1 * F4);
        float4 v2 = __ldcs(p + 2 * F4);
        float4 v3 = __ldcs(p + 3 * F4);
        float4 v4 = __ldcs(p + 4 * F4);
        float4 v5 = __ldcs(p + 5 * F4);
        float4 v6 = __ldcs(p + 6 * F4);
        float4 v7 = __ldcs(p + 7 * F4);
        a0.x += v0.x; a0.y += v0.y; a0.z += v0.z; a0.w += v0.w;
        a1.x += v1.x; a1.y += v1.y; a1.z += v1.z; a1.w += v1.w;
        a2.x += v2.x; a2.y += v2.y; a2.z += v2.z; a2.w += v2.w;
        a3.x += v3.x; a3.y += v3.y; a3.z += v3.z; a3.w += v3.w;
        a0.x += v4.x; a0.y += v4.y; a0.z += v4.z; a0.w += v4.w;
        a1.x += v5.x; a1.y += v5.y; a1.z += v5.z; a1.w += v5.w;
        a2.x += v6.x; a2.y += v6.y; a2.z += v6.z; a2.w += v6.w;
        a3.x += v7.x; a3.y += v7.y; a3.z += v7.z; a3.w += v7.w;
    }
    for (; n > 0; n--, p += F4) {
        float4 v = __ldcs(p);
        a0.x += v.x; a0.y += v.y; a0.z += v.z; a0.w += v.w;
    }
    a0.x += a1.x; a0.y += a1.y; a0.z += a1.z; a0.w += a1.w;
    a2.x += a3.x; a2.y += a3.y; a2.z += a3.z; a2.w += a3.w;
    a0.x += a2.x; a0.y += a2.y; a0.z += a2.z; a0.w += a2.w;

    // --- 7 partial dots against W (tiny, L2-resident; default caching)
    float pr[OUTK];
    #pragma unroll
    for (int k = 0; k < OUTK; k++) {
        float4 w = __ldg(&W4g[k * F4 + t]);
        pr[k] = a0.x * w.x + a0.y * w.y + a0.z * w.z + a0.w * w.w;
    }

    // --- reduce across 4 warps
    #pragma unroll
    for (int off = 16; off > 0; off >>= 1) {
        #pragma unroll
        for (int k = 0; k < OUTK; k++)
            pr[k] += __shfl_xor_sync(0xffffffff, pr[k], off);
    }
    if (lane == 0) {
        #pragma unroll
        for (int k = 0; k < OUTK; k++) redw[warp][k] = pr[k];
    }
    __syncthreads();

    if (t < OUTK) {
        float v = redw[0][t] + redw[1][t] + redw[2][t] + redw[3][t];
        out[g * OUTK + t] = v / fmaxf((float)cnt, 1.0f) + bias[t];
    }
}

// ---------------------------------------------------------------------------
// Inputs (metadata order):
//   d_in[0] = x          float32 [100000, 512]
//   d_in[1] = edge_index (unused)
//   d_in[2] = edge_attr  (unused)
//   d_in[3] = batch      int64-or-int32 [100000] (probed in-kernel)
//   d_in[4] = W          float32 [7, 512]
//   d_in[5] = b          float32 [7]
// Output: float32 [1024, 7]
// ---------------------------------------------------------------------------
extern "C" void kernel_launch(void* const* d_in, const int* in_sizes, int n_in,
                              void* d_out, int out_size)
{
    const float4* x4  = (const float4*)d_in[0];
    const int*    bw  = (const int*)d_in[3];
    const float4* W4g = (const float4*)d_in[4];
    const float*  b   = (const float*)d_in[5];
    float*        out = (float*)d_out;

    const int N = in_sizes[3];

    mognn_kernel<<<NGROUPS, TPB>>>(x4, bw, W4g, b, out, N);
}